// round 14
// baseline (speedup 1.0000x reference)
#include <cuda_runtime.h>
#include <cuda_fp16.h>
#include <cstdint>

// ===========================================================================
// GraphSageNet GB300 — round 13.
// conv1: 512 thr with 4-oc x 8-px per-thread tile (reg-safe: ~75 regs < 128
//        cap) -> 4 warps/SMSP, no spill. Bit-identical accumulation order.
// sage:  #pragma unroll 4 on the L2-streaming weight loops (MLP 1 -> 4+).
// conv2 / fc / prep: byte-identical to R12 (proven 698.5us config).
// ===========================================================================

#define NPAD 1280
#define GUARD 64
#define ROWS_TOTAL (GUARD + 1024 * NPAD + GUARD)

__device__ __align__(16) __half g_act[(size_t)ROWS_TOTAL * 64];
__device__ __align__(16) __half g_wh[2 * 9 * 4096];
__device__ __align__(16) float g_pp[1024 * 128];
__device__ __align__(16) float g_h1[1024 * 256];
__device__ __align__(16) float g_h2[1024 * 256];
__device__ __align__(16) float g_w21t[256 * 256];
__device__ __align__(16) float g_l1t [256 * 256];
__device__ __align__(16) float g_w22t[256 * 128];
__device__ __align__(16) float g_l2t [256 * 128];

// ------------------------------- helpers -----------------------------------
__device__ __forceinline__ uint32_t smem_u32(const void* p) {
    uint32_t a;
    asm("{ .reg .u64 t; cvta.to.shared.u64 t, %1; cvt.u32.u64 %0, t; }"
        : "=r"(a) : "l"(p));
    return a;
}
__device__ __forceinline__ void ldsm4(uint32_t* r, uint32_t addr) {
    asm volatile("ldmatrix.sync.aligned.m8n8.x4.shared.b16 {%0,%1,%2,%3}, [%4];"
                 : "=r"(r[0]), "=r"(r[1]), "=r"(r[2]), "=r"(r[3]) : "r"(addr));
}
__device__ __forceinline__ void mma16816(float* d, const uint32_t* a,
                                         uint32_t b0, uint32_t b1) {
    asm volatile(
        "mma.sync.aligned.m16n8k16.row.col.f32.f16.f16.f32 "
        "{%0,%1,%2,%3}, {%4,%5,%6,%7}, {%8,%9}, {%0,%1,%2,%3};"
        : "+f"(d[0]), "+f"(d[1]), "+f"(d[2]), "+f"(d[3])
        : "r"(a[0]), "r"(a[1]), "r"(a[2]), "r"(a[3]), "r"(b0), "r"(b1));
}
#define CPA16(dst, src) \
    asm volatile("cp.async.cg.shared.global [%0], [%1], 16;" \
                 :: "r"(dst), "l"(src) : "memory")
#define CPA_COMMIT() asm volatile("cp.async.commit_group;" ::: "memory")

__device__ __forceinline__ unsigned long long pack2(float lo, float hi) {
    unsigned long long d;
    asm("mov.b64 %0, {%1, %2};" : "=l"(d)
        : "r"(__float_as_uint(lo)), "r"(__float_as_uint(hi)));
    return d;
}
__device__ __forceinline__ void unpack2(unsigned long long v, float& lo, float& hi) {
    unsigned a, b;
    asm("mov.b64 {%0, %1}, %2;" : "=r"(a), "=r"(b) : "l"(v));
    lo = __uint_as_float(a); hi = __uint_as_float(b);
}
__device__ __forceinline__ void fma2(unsigned long long& d, unsigned long long a,
                                     unsigned long long b, unsigned long long c) {
    asm("fma.rn.f32x2 %0, %1, %2, %3;" : "=l"(d) : "l"(a), "l"(b), "l"(c));
}

// ---------------------------------------------------------------------------
// prep_all: conv2 weights -> fp16 SW128 tiles; sage folded weights
// ---------------------------------------------------------------------------
__global__ void prep_all(const float* __restrict__ w,
                         const float* __restrict__ s1lw,
                         const float* __restrict__ s1rw,
                         const float* __restrict__ s2lw,
                         const float* __restrict__ s2rw) {
    const float C = 1.f / 31.f;
    int idx = blockIdx.x * 256 + threadIdx.x;
    if (idx < 73728) {
        int s = idx % 9, t = idx / 9;
        int ic = t % 64, oc = t / 64;
        float v = w[oc * 576 + ic * 9 + s];
        int ocg = oc >> 6, ocl = oc & 63;
        uint32_t off = (uint32_t)(ocl * 128 + ic * 2);
        uint32_t sw = off ^ ((off >> 3) & 0x70);
        uint32_t base = ((uint32_t)ocg * 9 + (uint32_t)s) * 8192u;
        *(__half*)((char*)g_wh + base + sw) = __float2half_rn(v);
    } else {
        int j = idx - 73728;
        if (j < 65536) {
            int o = j >> 8, d = j & 255;
            float l = s1lw[j];
            g_w21t[d * 256 + o] = s1rw[j] - C * l;
            g_l1t [d * 256 + o] = l;
        } else if (j < 98304) {
            int j2 = j - 65536;
            int o = j2 >> 8, d = j2 & 255;
            float l = s2lw[j2];
            g_w22t[d * 128 + o] = s2rw[j2] - C * l;
            g_l2t [d * 128 + o] = l;
        }
    }
}

// ---------------------------------------------------------------------------
// conv1: [1024,3,32,32] -> relu -> fp16 padded px-major; packed f32x2 FMA.
// 512 threads: 16 warps = 16 oc-quads; each thread 4 oc x 8 px per it.
// ---------------------------------------------------------------------------
__global__ void __launch_bounds__(512) conv1_kernel(const float* __restrict__ x,
                                                    const float* __restrict__ w,
                                                    const float* __restrict__ b) {
    __shared__ __align__(16) float ws[27 * 64];
    __shared__ __align__(16) float xs[3 * 34 * 35];

    const int n = blockIdx.x, tid = threadIdx.x;

    for (int i = tid; i < 3 * 34 * 35; i += 512) xs[i] = 0.f;
    for (int i = tid; i < 64 * 27; i += 512) {
        int oc = i / 27, k = i % 27;
        ws[k * 64 + oc] = w[i];
    }
    __syncthreads();
    const float* xin = x + n * 3072;
    for (int i = tid; i < 3072; i += 512) {
        int ic = i >> 10, r = (i >> 5) & 31, c = i & 31;
        xs[ic * (34 * 35) + (r + 1) * 35 + (c + 1)] = xin[i];
    }
    __syncthreads();

    const int wid = tid >> 5, lane = tid & 31;
    const int oc0 = wid * 4;
    unsigned long long bp[4];
#pragma unroll
    for (int j = 0; j < 4; j++) {
        float bv = b[oc0 + j];
        bp[j] = pack2(bv, bv);
    }

    for (int it = 0; it < 4; it++) {
        int pg = it * 32 + lane;
        int row = pg >> 2, colb = (pg & 3) * 8;
        unsigned long long acc[4][4];
#pragma unroll
        for (int j = 0; j < 4; j++)
#pragma unroll
            for (int t = 0; t < 4; t++) acc[j][t] = bp[j];

#pragma unroll
        for (int ic = 0; ic < 3; ic++)
#pragma unroll
            for (int kr = 0; kr < 3; kr++) {
                int base = ic * (34 * 35) + (row + kr) * 35 + colb;
                float in10[10];
#pragma unroll
                for (int q = 0; q < 10; q++) in10[q] = xs[base + q];
#pragma unroll
                for (int kc = 0; kc < 3; kc++) {
                    int k = ic * 9 + kr * 3 + kc;
                    float4 w0 = *(const float4*)&ws[k * 64 + oc0];
                    float wv[4] = {w0.x, w0.y, w0.z, w0.w};
                    unsigned long long ip[4];
#pragma unroll
                    for (int t = 0; t < 4; t++)
                        ip[t] = pack2(in10[kc + 2 * t], in10[kc + 2 * t + 1]);
#pragma unroll
                    for (int j = 0; j < 4; j++) {
                        unsigned long long wp = pack2(wv[j], wv[j]);
#pragma unroll
                        for (int t = 0; t < 4; t++) fma2(acc[j][t], wp, ip[t], acc[j][t]);
                    }
                }
            }
#pragma unroll
        for (int p = 0; p < 8; p++) {
            int col = colb + p;
            size_t pxa = (size_t)GUARD + (size_t)n * NPAD + (row + 1) * 34 + (col + 1);
            uint32_t q[2];
#pragma unroll
            for (int pr = 0; pr < 2; pr++) {
                float a0l, a0h, a1l, a1h;
                unpack2(acc[2 * pr][p >> 1], a0l, a0h);
                unpack2(acc[2 * pr + 1][p >> 1], a1l, a1h);
                float v0 = (p & 1) ? a0h : a0l;
                float v1 = (p & 1) ? a1h : a1l;
                __half h0 = __float2half_rn(fmaxf(v0, 0.f));
                __half h1 = __float2half_rn(fmaxf(v1, 0.f));
                q[pr] = (uint32_t)__half_as_ushort(h0) |
                        ((uint32_t)__half_as_ushort(h1) << 16);
            }
            *(uint2*)&g_act[pxa * 64 + oc0] = make_uint2(q[0], q[1]);
        }
    }
}

// ---------------------------------------------------------------------------
// conv2 (R10/R12 proven): grid 1024, 512 thr, triple-buffered slab ring.
// ---------------------------------------------------------------------------
#define SM_WH 0
#define SM_SLAB 147456
#define SLAB_BYTES 25344
#define SM_BIAS (SM_SLAB + 3 * SLAB_BYTES)
#define SM_RED (SM_BIAS + 512)
#define C2_SMEM (SM_RED + 2048)

__device__ __forceinline__ void stage_slab(uint32_t sbase, const uint4* src, int tid) {
    for (int i = tid; i < 1584; i += 512) {
        int r = i >> 3, j = i & 7;
        uint32_t d = (uint32_t)(r * 128) +
                     (((uint32_t)(j * 16)) ^ ((uint32_t)((r & 7) << 4)));
        CPA16(sbase + d, src + (size_t)r * 8 + j);
    }
}

__global__ void __launch_bounds__(512, 1) conv2_mma(const float* __restrict__ bias) {
    extern __shared__ __align__(1024) char smc[];
    const uint32_t smb = smem_u32(smc);
    const int tid = threadIdx.x, wid = tid >> 5, lane = tid & 31;
    const int n = blockIdx.x;
    const int pxw = wid & 3, ocw = wid >> 2;

    const size_t img_base = (size_t)GUARD + (size_t)n * NPAD;
    const uint4* slab0 = (const uint4*)g_act + (img_base - 35) * 8;

    {
        const uint4* srcH = (const uint4*)g_wh;
        for (int i = tid; i < 9216; i += 512)
            CPA16(smb + SM_WH + i * 16, srcH + i);
        stage_slab(smb + SM_SLAB, slab0, tid);
        CPA_COMMIT();
        stage_slab(smb + SM_SLAB + SLAB_BYTES, slab0 + 1024, tid);
        CPA_COMMIT();
    }
    if (tid < 128) ((float*)(smc + SM_BIAS))[tid] = bias[tid];

    const int l15 = lane & 15;
    const uint32_t lk = (uint32_t)((lane >> 4) * 16);
    const uint32_t wgBase = (uint32_t)((ocw >> 1) * 9) * 8192u;
    const int rB0 = (ocw & 1) * 32 + l15, rB1 = rB0 + 16;
    const uint32_t swB0 = (uint32_t)((rB0 & 7) << 4);
    const uint32_t swB1 = (uint32_t)((rB1 & 7) << 4);

    float b8[8];
#pragma unroll
    for (int nt = 0; nt < 4; nt++)
#pragma unroll
        for (int bb = 0; bb < 2; bb++)
            b8[nt * 2 + bb] = bias[ocw * 32 + nt * 8 + (lane & 3) * 2 + bb];

    float psum[8];
#pragma unroll
    for (int i = 0; i < 8; i++) psum[i] = 0.f;

    for (int t = 0; t < 9; t++) {
        if (t < 8) {
            asm volatile("cp.async.wait_group 1;" ::: "memory");
        } else {
            asm volatile("cp.async.wait_group 0;" ::: "memory");
        }
        __syncthreads();
        if (t < 7) {
            stage_slab(smb + SM_SLAB + (uint32_t)(((t + 2) % 3) * SLAB_BYTES),
                       slab0 + (size_t)(t + 2) * 1024, tid);
            CPA_COMMIT();
        }

        const uint32_t sbA = smb + SM_SLAB + (uint32_t)((t % 3) * SLAB_BYTES);
        float acc[2][4][4];
#pragma unroll
        for (int mt = 0; mt < 2; mt++)
#pragma unroll
            for (int nt = 0; nt < 4; nt++)
#pragma unroll
                for (int rg = 0; rg < 4; rg++) acc[mt][nt][rg] = 0.f;

#pragma unroll
        for (int s = 0; s < 9; s++) {
            const int doff = (s / 3 - 1) * 34 + (s % 3 - 1);
            const int rA0 = 35 + doff + pxw * 32 + l15;
            const int rA1 = rA0 + 16;
            const uint32_t swA0 = (uint32_t)((rA0 & 7) << 4);
            const uint32_t swA1 = (uint32_t)((rA1 & 7) << 4);
            const uint32_t wt = wgBase + (uint32_t)(s * 8192);
#pragma unroll
            for (int k = 0; k < 4; k++) {
                const uint32_t kb = (uint32_t)(k * 32) + lk;
                uint32_t a0[4], a1[4], bh0[4], bh1[4];
                ldsm4(a0, sbA + (uint32_t)(rA0 * 128) + (kb ^ swA0));
                ldsm4(a1, sbA + (uint32_t)(rA1 * 128) + (kb ^ swA1));
                ldsm4(bh0, smb + SM_WH + wt + (uint32_t)(rB0 * 128) + (kb ^ swB0));
                ldsm4(bh1, smb + SM_WH + wt + (uint32_t)(rB1 * 128) + (kb ^ swB1));
                mma16816(acc[0][0], a0, bh0[0], bh0[2]);
                mma16816(acc[0][1], a0, bh0[1], bh0[3]);
                mma16816(acc[0][2], a0, bh1[0], bh1[2]);
                mma16816(acc[0][3], a0, bh1[1], bh1[3]);
                mma16816(acc[1][0], a1, bh0[0], bh0[2]);
                mma16816(acc[1][1], a1, bh0[1], bh0[3]);
                mma16816(acc[1][2], a1, bh1[0], bh1[2]);
                mma16816(acc[1][3], a1, bh1[1], bh1[3]);
            }
        }

        bool inter[2][2];
#pragma unroll
        for (int mt = 0; mt < 2; mt++)
#pragma unroll
            for (int hh = 0; hh < 2; hh++) {
                int pl = t * 128 + pxw * 32 + mt * 16 + (lane >> 2) + hh * 8;
                int rr = pl / 34, cc = pl - rr * 34;
                inter[mt][hh] =
                    (pl < 1156) & (rr >= 1) & (rr <= 32) & (cc >= 1) & (cc <= 32);
            }
#pragma unroll
        for (int mt = 0; mt < 2; mt++)
#pragma unroll
            for (int nt = 0; nt < 4; nt++)
#pragma unroll
                for (int rg = 0; rg < 4; rg++) {
                    float v = fmaxf(acc[mt][nt][rg] + b8[nt * 2 + (rg & 1)], 0.f);
                    if (inter[mt][rg >> 1]) psum[nt * 2 + (rg & 1)] += v;
                }
    }

#pragma unroll
    for (int off = 4; off <= 16; off <<= 1)
#pragma unroll
        for (int i = 0; i < 8; i++)
            psum[i] += __shfl_xor_sync(0xffffffffu, psum[i], off);

    float* red = (float*)(smc + SM_RED);
    if (lane < 4) {
#pragma unroll
        for (int nt = 0; nt < 4; nt++)
#pragma unroll
            for (int bb = 0; bb < 2; bb++)
                red[wid * 32 + nt * 8 + lane * 2 + bb] = psum[nt * 2 + bb];
    }
    __syncthreads();
    if (tid < 128) {
        int og = tid >> 5, c = tid & 31;
        float s = 0.f;
#pragma unroll
        for (int p = 0; p < 4; p++) s += red[(og * 4 + p) * 32 + c];
        g_pp[n * 128 + og * 32 + c] = s;
    }
}

// ---------------------------------------------------------------------------
// fc: (g_pp/1024) [1024,128] @ fc_w.T + fc_b, * mask -> g_h1 (proven 26us)
// ---------------------------------------------------------------------------
#define FC_SMEM_BYTES ((128 * 256 + 8 * 128) * 4)

__global__ void __launch_bounds__(256) fc_kernel(const float* __restrict__ fcw,
                                                 const float* __restrict__ fcb,
                                                 const float* __restrict__ mask) {
    extern __shared__ __align__(16) float smf[];
    float* ws = smf;
    float* ps = smf + 128 * 256;
    const int row0 = blockIdx.x * 8, tid = threadIdx.x;

    for (int i = tid; i < 128 * 256; i += 256) {
        int o = i >> 7, d = i & 127;
        ws[d * 256 + o] = fcw[i];
    }
    for (int i = tid; i < 8 * 128; i += 256)
        ps[i] = g_pp[row0 * 128 + i] * (1.f / 1024.f);
    __syncthreads();

    const int o = tid;
    float acc[8];
    float bb = fcb[o];
#pragma unroll
    for (int rr = 0; rr < 8; rr++) acc[rr] = bb;
    for (int d = 0; d < 128; d++) {
        float wv = ws[d * 256 + o];
#pragma unroll
        for (int rr = 0; rr < 8; rr++) acc[rr] = fmaf(ps[rr * 128 + d], wv, acc[rr]);
    }
#pragma unroll
    for (int rr = 0; rr < 8; rr++) {
        int row = row0 + rr;
        g_h1[row * 256 + o] = acc[rr] * mask[row];
    }
}

// ---------------------------------------------------------------------------
// SAGE layer, folded weights: out = h @ W2^T + [cs @ lw^T / 31 + lb]
// grid (32 b, 4 segs of 8 nodes); weight loops unrolled for MLP.
// ---------------------------------------------------------------------------
template <int OUTD, bool RELU, bool FROM_H1>
__global__ void __launch_bounds__(256) sage_kernel(const float* __restrict__ lb,
                                                   float* __restrict__ out) {
    __shared__ __align__(16) float hs[32 * 260];
    __shared__ float CS[256];
    const int b = blockIdx.x, tid = threadIdx.x;
    const int n0 = blockIdx.y * 8;
    const float* hb = (FROM_H1 ? g_h1 : g_h2) + b * 8192;

    for (int i = tid; i < 8192; i += 256) {
        int nn = i >> 8, d = i & 255;
        hs[nn * 260 + d] = hb[i];
    }
    __syncthreads();
    {
        const int d = tid;
        float s = 0.f;
#pragma unroll
        for (int nn = 0; nn < 32; nn++) s += hs[nn * 260 + d];
        CS[d] = s;
    }
    __syncthreads();

    const float* lt = (OUTD == 256) ? g_l1t : g_l2t;
    const float* wt = (OUTD == 256) ? g_w21t : g_w22t;
    const int o = tid;
    if (o < OUTD) {
        float v = 0.f;
#pragma unroll 4
        for (int d = 0; d < 256; d += 4)
            v += CS[d] * lt[d * OUTD + o] + CS[d + 1] * lt[(d + 1) * OUTD + o] +
                 CS[d + 2] * lt[(d + 2) * OUTD + o] +
                 CS[d + 3] * lt[(d + 3) * OUTD + o];
        float init = v * (1.f / 31.f) + lb[o];
        float acc[8];
#pragma unroll
        for (int nn = 0; nn < 8; nn++) acc[nn] = init;
#pragma unroll 8
        for (int d = 0; d < 256; d++) {
            float w = wt[d * OUTD + o];
#pragma unroll
            for (int nn = 0; nn < 8; nn++)
                acc[nn] = fmaf(hs[(n0 + nn) * 260 + d], w, acc[nn]);
        }
#pragma unroll
        for (int nn = 0; nn < 8; nn++) {
            float r = acc[nn];
            if (RELU) r = fmaxf(r, 0.f);
            if (OUTD == 256)
                g_h2[(b * 32 + n0 + nn) * 256 + o] = r;
            else
                out[(b * 32 + n0 + nn) * OUTD + o] = r;
        }
    }
}

// ---------------------------------------------------------------------------
extern "C" void kernel_launch(void* const* d_in, const int* in_sizes, int n_in,
                              void* d_out, int out_size) {
    const float* x    = (const float*)d_in[0];
    const float* mask = (const float*)d_in[1];
    const float* c1w  = (const float*)d_in[2];
    const float* c1b  = (const float*)d_in[3];
    const float* c2w  = (const float*)d_in[4];
    const float* c2b  = (const float*)d_in[5];
    const float* fcw  = (const float*)d_in[6];
    const float* fcb  = (const float*)d_in[7];
    const float* s1lw = (const float*)d_in[8];
    const float* s1lb = (const float*)d_in[9];
    const float* s1rw = (const float*)d_in[10];
    const float* s2lw = (const float*)d_in[11];
    const float* s2lb = (const float*)d_in[12];
    const float* s2rw = (const float*)d_in[13];
    float* out = (float*)d_out;

    cudaFuncSetAttribute(conv2_mma, cudaFuncAttributeMaxDynamicSharedMemorySize,
                         C2_SMEM);
    cudaFuncSetAttribute(fc_kernel, cudaFuncAttributeMaxDynamicSharedMemorySize,
                         FC_SMEM_BYTES);

    prep_all<<<672, 256>>>(c2w, s1lw, s1rw, s2lw, s2rw);
    conv1_kernel<<<1024, 512>>>(x, c1w, c1b);
    conv2_mma<<<1024, 512, C2_SMEM>>>(c2b);
    fc_kernel<<<128, 256, FC_SMEM_BYTES>>>(fcw, fcb, mask);
    sage_kernel<256, true, true><<<dim3(32, 4), 256>>>(s1lb, out);
    sage_kernel<128, false, false><<<dim3(32, 4), 256>>>(s2lb, out);
}

// round 15
// speedup vs baseline: 1.0081x; 1.0081x over previous
#include <cuda_runtime.h>
#include <cuda_fp16.h>
#include <cstdint>

// ===========================================================================
// GraphSageNet GB300 — round 14.
// conv1: R12 body (256 thr, 8oc x 8px — proven compute density) with
//        __launch_bounds__(256, 2): caps regs at 128 -> 2 CTAs/SM ->
//        4 warps/SMSP with UNCHANGED per-thread workload. (R13's lever —
//        more threads, smaller tile — halved FMA/LDS amortization; reverted.)
// conv2 / fc / prep: byte-identical to R12 (proven 698.5us config).
// sage: R12 + unroll pragmas (MLP for L2 weight stream).
// ===========================================================================

#define NPAD 1280
#define GUARD 64
#define ROWS_TOTAL (GUARD + 1024 * NPAD + GUARD)

__device__ __align__(16) __half g_act[(size_t)ROWS_TOTAL * 64];
__device__ __align__(16) __half g_wh[2 * 9 * 4096];
__device__ __align__(16) float g_pp[1024 * 128];
__device__ __align__(16) float g_h1[1024 * 256];
__device__ __align__(16) float g_h2[1024 * 256];
__device__ __align__(16) float g_w21t[256 * 256];
__device__ __align__(16) float g_l1t [256 * 256];
__device__ __align__(16) float g_w22t[256 * 128];
__device__ __align__(16) float g_l2t [256 * 128];

// ------------------------------- helpers -----------------------------------
__device__ __forceinline__ uint32_t smem_u32(const void* p) {
    uint32_t a;
    asm("{ .reg .u64 t; cvta.to.shared.u64 t, %1; cvt.u32.u64 %0, t; }"
        : "=r"(a) : "l"(p));
    return a;
}
__device__ __forceinline__ void ldsm4(uint32_t* r, uint32_t addr) {
    asm volatile("ldmatrix.sync.aligned.m8n8.x4.shared.b16 {%0,%1,%2,%3}, [%4];"
                 : "=r"(r[0]), "=r"(r[1]), "=r"(r[2]), "=r"(r[3]) : "r"(addr));
}
__device__ __forceinline__ void mma16816(float* d, const uint32_t* a,
                                         uint32_t b0, uint32_t b1) {
    asm volatile(
        "mma.sync.aligned.m16n8k16.row.col.f32.f16.f16.f32 "
        "{%0,%1,%2,%3}, {%4,%5,%6,%7}, {%8,%9}, {%0,%1,%2,%3};"
        : "+f"(d[0]), "+f"(d[1]), "+f"(d[2]), "+f"(d[3])
        : "r"(a[0]), "r"(a[1]), "r"(a[2]), "r"(a[3]), "r"(b0), "r"(b1));
}
#define CPA16(dst, src) \
    asm volatile("cp.async.cg.shared.global [%0], [%1], 16;" \
                 :: "r"(dst), "l"(src) : "memory")
#define CPA_COMMIT() asm volatile("cp.async.commit_group;" ::: "memory")

__device__ __forceinline__ unsigned long long pack2(float lo, float hi) {
    unsigned long long d;
    asm("mov.b64 %0, {%1, %2};" : "=l"(d)
        : "r"(__float_as_uint(lo)), "r"(__float_as_uint(hi)));
    return d;
}
__device__ __forceinline__ void unpack2(unsigned long long v, float& lo, float& hi) {
    unsigned a, b;
    asm("mov.b64 {%0, %1}, %2;" : "=r"(a), "=r"(b) : "l"(v));
    lo = __uint_as_float(a); hi = __uint_as_float(b);
}
__device__ __forceinline__ void fma2(unsigned long long& d, unsigned long long a,
                                     unsigned long long b, unsigned long long c) {
    asm("fma.rn.f32x2 %0, %1, %2, %3;" : "=l"(d) : "l"(a), "l"(b), "l"(c));
}

// ---------------------------------------------------------------------------
// prep_all: conv2 weights -> fp16 SW128 tiles; sage folded weights
// ---------------------------------------------------------------------------
__global__ void prep_all(const float* __restrict__ w,
                         const float* __restrict__ s1lw,
                         const float* __restrict__ s1rw,
                         const float* __restrict__ s2lw,
                         const float* __restrict__ s2rw) {
    const float C = 1.f / 31.f;
    int idx = blockIdx.x * 256 + threadIdx.x;
    if (idx < 73728) {
        int s = idx % 9, t = idx / 9;
        int ic = t % 64, oc = t / 64;
        float v = w[oc * 576 + ic * 9 + s];
        int ocg = oc >> 6, ocl = oc & 63;
        uint32_t off = (uint32_t)(ocl * 128 + ic * 2);
        uint32_t sw = off ^ ((off >> 3) & 0x70);
        uint32_t base = ((uint32_t)ocg * 9 + (uint32_t)s) * 8192u;
        *(__half*)((char*)g_wh + base + sw) = __float2half_rn(v);
    } else {
        int j = idx - 73728;
        if (j < 65536) {
            int o = j >> 8, d = j & 255;
            float l = s1lw[j];
            g_w21t[d * 256 + o] = s1rw[j] - C * l;
            g_l1t [d * 256 + o] = l;
        } else if (j < 98304) {
            int j2 = j - 65536;
            int o = j2 >> 8, d = j2 & 255;
            float l = s2lw[j2];
            g_w22t[d * 128 + o] = s2rw[j2] - C * l;
            g_l2t [d * 128 + o] = l;
        }
    }
}

// ---------------------------------------------------------------------------
// conv1: [1024,3,32,32] -> relu -> fp16 padded px-major; packed f32x2 FMA.
// 256 thr, 8oc x 8px tile; __launch_bounds__(256,2) -> 2 CTAs/SM.
// ---------------------------------------------------------------------------
__global__ void __launch_bounds__(256, 2) conv1_kernel(const float* __restrict__ x,
                                                       const float* __restrict__ w,
                                                       const float* __restrict__ b) {
    __shared__ __align__(16) float ws[27 * 64];
    __shared__ __align__(16) float xs[3 * 34 * 35];

    const int n = blockIdx.x, tid = threadIdx.x;

    for (int i = tid; i < 3 * 34 * 35; i += 256) xs[i] = 0.f;
    for (int i = tid; i < 64 * 27; i += 256) {
        int oc = i / 27, k = i % 27;
        ws[k * 64 + oc] = w[i];
    }
    __syncthreads();
    const float* xin = x + n * 3072;
    for (int i = tid; i < 3072; i += 256) {
        int ic = i >> 10, r = (i >> 5) & 31, c = i & 31;
        xs[ic * (34 * 35) + (r + 1) * 35 + (c + 1)] = xin[i];
    }
    __syncthreads();

    const int ocq = tid >> 5, oc0 = ocq * 8;
    unsigned long long bp[8];
#pragma unroll
    for (int j = 0; j < 8; j++) {
        float bv = b[oc0 + j];
        bp[j] = pack2(bv, bv);
    }

    for (int it = 0; it < 4; it++) {
        int pg = it * 32 + (tid & 31);
        int row = pg >> 2, colb = (pg & 3) * 8;
        unsigned long long acc[8][4];
#pragma unroll
        for (int j = 0; j < 8; j++)
#pragma unroll
            for (int t = 0; t < 4; t++) acc[j][t] = bp[j];

#pragma unroll
        for (int ic = 0; ic < 3; ic++)
#pragma unroll
            for (int kr = 0; kr < 3; kr++) {
                int base = ic * (34 * 35) + (row + kr) * 35 + colb;
                float in10[10];
#pragma unroll
                for (int q = 0; q < 10; q++) in10[q] = xs[base + q];
#pragma unroll
                for (int kc = 0; kc < 3; kc++) {
                    int k = ic * 9 + kr * 3 + kc;
                    float4 w0 = *(const float4*)&ws[k * 64 + oc0];
                    float4 w1 = *(const float4*)&ws[k * 64 + oc0 + 4];
                    float wv[8] = {w0.x, w0.y, w0.z, w0.w, w1.x, w1.y, w1.z, w1.w};
                    unsigned long long ip[4];
#pragma unroll
                    for (int t = 0; t < 4; t++)
                        ip[t] = pack2(in10[kc + 2 * t], in10[kc + 2 * t + 1]);
#pragma unroll
                    for (int j = 0; j < 8; j++) {
                        unsigned long long wp = pack2(wv[j], wv[j]);
#pragma unroll
                        for (int t = 0; t < 4; t++) fma2(acc[j][t], wp, ip[t], acc[j][t]);
                    }
                }
            }
#pragma unroll
        for (int p = 0; p < 8; p++) {
            int col = colb + p;
            size_t pxa = (size_t)GUARD + (size_t)n * NPAD + (row + 1) * 34 + (col + 1);
            uint32_t q[4];
#pragma unroll
            for (int pr = 0; pr < 4; pr++) {
                float a0l, a0h, a1l, a1h;
                unpack2(acc[2 * pr][p >> 1], a0l, a0h);
                unpack2(acc[2 * pr + 1][p >> 1], a1l, a1h);
                float v0 = (p & 1) ? a0h : a0l;
                float v1 = (p & 1) ? a1h : a1l;
                __half h0 = __float2half_rn(fmaxf(v0, 0.f));
                __half h1 = __float2half_rn(fmaxf(v1, 0.f));
                q[pr] = (uint32_t)__half_as_ushort(h0) |
                        ((uint32_t)__half_as_ushort(h1) << 16);
            }
            *(uint4*)&g_act[pxa * 64 + oc0] = make_uint4(q[0], q[1], q[2], q[3]);
        }
    }
}

// ---------------------------------------------------------------------------
// conv2 (R10/R12 proven): grid 1024, 512 thr, triple-buffered slab ring.
// ---------------------------------------------------------------------------
#define SM_WH 0
#define SM_SLAB 147456
#define SLAB_BYTES 25344
#define SM_BIAS (SM_SLAB + 3 * SLAB_BYTES)
#define SM_RED (SM_BIAS + 512)
#define C2_SMEM (SM_RED + 2048)

__device__ __forceinline__ void stage_slab(uint32_t sbase, const uint4* src, int tid) {
    for (int i = tid; i < 1584; i += 512) {
        int r = i >> 3, j = i & 7;
        uint32_t d = (uint32_t)(r * 128) +
                     (((uint32_t)(j * 16)) ^ ((uint32_t)((r & 7) << 4)));
        CPA16(sbase + d, src + (size_t)r * 8 + j);
    }
}

__global__ void __launch_bounds__(512, 1) conv2_mma(const float* __restrict__ bias) {
    extern __shared__ __align__(1024) char smc[];
    const uint32_t smb = smem_u32(smc);
    const int tid = threadIdx.x, wid = tid >> 5, lane = tid & 31;
    const int n = blockIdx.x;
    const int pxw = wid & 3, ocw = wid >> 2;

    const size_t img_base = (size_t)GUARD + (size_t)n * NPAD;
    const uint4* slab0 = (const uint4*)g_act + (img_base - 35) * 8;

    {
        const uint4* srcH = (const uint4*)g_wh;
        for (int i = tid; i < 9216; i += 512)
            CPA16(smb + SM_WH + i * 16, srcH + i);
        stage_slab(smb + SM_SLAB, slab0, tid);
        CPA_COMMIT();
        stage_slab(smb + SM_SLAB + SLAB_BYTES, slab0 + 1024, tid);
        CPA_COMMIT();
    }
    if (tid < 128) ((float*)(smc + SM_BIAS))[tid] = bias[tid];

    const int l15 = lane & 15;
    const uint32_t lk = (uint32_t)((lane >> 4) * 16);
    const uint32_t wgBase = (uint32_t)((ocw >> 1) * 9) * 8192u;
    const int rB0 = (ocw & 1) * 32 + l15, rB1 = rB0 + 16;
    const uint32_t swB0 = (uint32_t)((rB0 & 7) << 4);
    const uint32_t swB1 = (uint32_t)((rB1 & 7) << 4);

    float b8[8];
#pragma unroll
    for (int nt = 0; nt < 4; nt++)
#pragma unroll
        for (int bb = 0; bb < 2; bb++)
            b8[nt * 2 + bb] = bias[ocw * 32 + nt * 8 + (lane & 3) * 2 + bb];

    float psum[8];
#pragma unroll
    for (int i = 0; i < 8; i++) psum[i] = 0.f;

    for (int t = 0; t < 9; t++) {
        if (t < 8) {
            asm volatile("cp.async.wait_group 1;" ::: "memory");
        } else {
            asm volatile("cp.async.wait_group 0;" ::: "memory");
        }
        __syncthreads();
        if (t < 7) {
            stage_slab(smb + SM_SLAB + (uint32_t)(((t + 2) % 3) * SLAB_BYTES),
                       slab0 + (size_t)(t + 2) * 1024, tid);
            CPA_COMMIT();
        }

        const uint32_t sbA = smb + SM_SLAB + (uint32_t)((t % 3) * SLAB_BYTES);
        float acc[2][4][4];
#pragma unroll
        for (int mt = 0; mt < 2; mt++)
#pragma unroll
            for (int nt = 0; nt < 4; nt++)
#pragma unroll
                for (int rg = 0; rg < 4; rg++) acc[mt][nt][rg] = 0.f;

#pragma unroll
        for (int s = 0; s < 9; s++) {
            const int doff = (s / 3 - 1) * 34 + (s % 3 - 1);
            const int rA0 = 35 + doff + pxw * 32 + l15;
            const int rA1 = rA0 + 16;
            const uint32_t swA0 = (uint32_t)((rA0 & 7) << 4);
            const uint32_t swA1 = (uint32_t)((rA1 & 7) << 4);
            const uint32_t wt = wgBase + (uint32_t)(s * 8192);
#pragma unroll
            for (int k = 0; k < 4; k++) {
                const uint32_t kb = (uint32_t)(k * 32) + lk;
                uint32_t a0[4], a1[4], bh0[4], bh1[4];
                ldsm4(a0, sbA + (uint32_t)(rA0 * 128) + (kb ^ swA0));
                ldsm4(a1, sbA + (uint32_t)(rA1 * 128) + (kb ^ swA1));
                ldsm4(bh0, smb + SM_WH + wt + (uint32_t)(rB0 * 128) + (kb ^ swB0));
                ldsm4(bh1, smb + SM_WH + wt + (uint32_t)(rB1 * 128) + (kb ^ swB1));
                mma16816(acc[0][0], a0, bh0[0], bh0[2]);
                mma16816(acc[0][1], a0, bh0[1], bh0[3]);
                mma16816(acc[0][2], a0, bh1[0], bh1[2]);
                mma16816(acc[0][3], a0, bh1[1], bh1[3]);
                mma16816(acc[1][0], a1, bh0[0], bh0[2]);
                mma16816(acc[1][1], a1, bh0[1], bh0[3]);
                mma16816(acc[1][2], a1, bh1[0], bh1[2]);
                mma16816(acc[1][3], a1, bh1[1], bh1[3]);
            }
        }

        bool inter[2][2];
#pragma unroll
        for (int mt = 0; mt < 2; mt++)
#pragma unroll
            for (int hh = 0; hh < 2; hh++) {
                int pl = t * 128 + pxw * 32 + mt * 16 + (lane >> 2) + hh * 8;
                int rr = pl / 34, cc = pl - rr * 34;
                inter[mt][hh] =
                    (pl < 1156) & (rr >= 1) & (rr <= 32) & (cc >= 1) & (cc <= 32);
            }
#pragma unroll
        for (int mt = 0; mt < 2; mt++)
#pragma unroll
            for (int nt = 0; nt < 4; nt++)
#pragma unroll
                for (int rg = 0; rg < 4; rg++) {
                    float v = fmaxf(acc[mt][nt][rg] + b8[nt * 2 + (rg & 1)], 0.f);
                    if (inter[mt][rg >> 1]) psum[nt * 2 + (rg & 1)] += v;
                }
    }

#pragma unroll
    for (int off = 4; off <= 16; off <<= 1)
#pragma unroll
        for (int i = 0; i < 8; i++)
            psum[i] += __shfl_xor_sync(0xffffffffu, psum[i], off);

    float* red = (float*)(smc + SM_RED);
    if (lane < 4) {
#pragma unroll
        for (int nt = 0; nt < 4; nt++)
#pragma unroll
            for (int bb = 0; bb < 2; bb++)
                red[wid * 32 + nt * 8 + lane * 2 + bb] = psum[nt * 2 + bb];
    }
    __syncthreads();
    if (tid < 128) {
        int og = tid >> 5, c = tid & 31;
        float s = 0.f;
#pragma unroll
        for (int p = 0; p < 4; p++) s += red[(og * 4 + p) * 32 + c];
        g_pp[n * 128 + og * 32 + c] = s;
    }
}

// ---------------------------------------------------------------------------
// fc: (g_pp/1024) [1024,128] @ fc_w.T + fc_b, * mask -> g_h1 (proven 26us)
// ---------------------------------------------------------------------------
#define FC_SMEM_BYTES ((128 * 256 + 8 * 128) * 4)

__global__ void __launch_bounds__(256) fc_kernel(const float* __restrict__ fcw,
                                                 const float* __restrict__ fcb,
                                                 const float* __restrict__ mask) {
    extern __shared__ __align__(16) float smf[];
    float* ws = smf;
    float* ps = smf + 128 * 256;
    const int row0 = blockIdx.x * 8, tid = threadIdx.x;

    for (int i = tid; i < 128 * 256; i += 256) {
        int o = i >> 7, d = i & 127;
        ws[d * 256 + o] = fcw[i];
    }
    for (int i = tid; i < 8 * 128; i += 256)
        ps[i] = g_pp[row0 * 128 + i] * (1.f / 1024.f);
    __syncthreads();

    const int o = tid;
    float acc[8];
    float bb = fcb[o];
#pragma unroll
    for (int rr = 0; rr < 8; rr++) acc[rr] = bb;
    for (int d = 0; d < 128; d++) {
        float wv = ws[d * 256 + o];
#pragma unroll
        for (int rr = 0; rr < 8; rr++) acc[rr] = fmaf(ps[rr * 128 + d], wv, acc[rr]);
    }
#pragma unroll
    for (int rr = 0; rr < 8; rr++) {
        int row = row0 + rr;
        g_h1[row * 256 + o] = acc[rr] * mask[row];
    }
}

// ---------------------------------------------------------------------------
// SAGE layer, folded weights: out = h @ W2^T + [cs @ lw^T / 31 + lb]
// grid (32 b, 4 segs of 8 nodes); weight loops unrolled for MLP.
// ---------------------------------------------------------------------------
template <int OUTD, bool RELU, bool FROM_H1>
__global__ void __launch_bounds__(256) sage_kernel(const float* __restrict__ lb,
                                                   float* __restrict__ out) {
    __shared__ __align__(16) float hs[32 * 260];
    __shared__ float CS[256];
    const int b = blockIdx.x, tid = threadIdx.x;
    const int n0 = blockIdx.y * 8;
    const float* hb = (FROM_H1 ? g_h1 : g_h2) + b * 8192;

    for (int i = tid; i < 8192; i += 256) {
        int nn = i >> 8, d = i & 255;
        hs[nn * 260 + d] = hb[i];
    }
    __syncthreads();
    {
        const int d = tid;
        float s = 0.f;
#pragma unroll
        for (int nn = 0; nn < 32; nn++) s += hs[nn * 260 + d];
        CS[d] = s;
    }
    __syncthreads();

    const float* lt = (OUTD == 256) ? g_l1t : g_l2t;
    const float* wt = (OUTD == 256) ? g_w21t : g_w22t;
    const int o = tid;
    if (o < OUTD) {
        float v = 0.f;
#pragma unroll 4
        for (int d = 0; d < 256; d += 4)
            v += CS[d] * lt[d * OUTD + o] + CS[d + 1] * lt[(d + 1) * OUTD + o] +
                 CS[d + 2] * lt[(d + 2) * OUTD + o] +
                 CS[d + 3] * lt[(d + 3) * OUTD + o];
        float init = v * (1.f / 31.f) + lb[o];
        float acc[8];
#pragma unroll
        for (int nn = 0; nn < 8; nn++) acc[nn] = init;
#pragma unroll 8
        for (int d = 0; d < 256; d++) {
            float w = wt[d * OUTD + o];
#pragma unroll
            for (int nn = 0; nn < 8; nn++)
                acc[nn] = fmaf(hs[(n0 + nn) * 260 + d], w, acc[nn]);
        }
#pragma unroll
        for (int nn = 0; nn < 8; nn++) {
            float r = acc[nn];
            if (RELU) r = fmaxf(r, 0.f);
            if (OUTD == 256)
                g_h2[(b * 32 + n0 + nn) * 256 + o] = r;
            else
                out[(b * 32 + n0 + nn) * OUTD + o] = r;
        }
    }
}

// ---------------------------------------------------------------------------
extern "C" void kernel_launch(void* const* d_in, const int* in_sizes, int n_in,
                              void* d_out, int out_size) {
    const float* x    = (const float*)d_in[0];
    const float* mask = (const float*)d_in[1];
    const float* c1w  = (const float*)d_in[2];
    const float* c1b  = (const float*)d_in[3];
    const float* c2w  = (const float*)d_in[4];
    const float* c2b  = (const float*)d_in[5];
    const float* fcw  = (const float*)d_in[6];
    const float* fcb  = (const float*)d_in[7];
    const float* s1lw = (const float*)d_in[8];
    const float* s1lb = (const float*)d_in[9];
    const float* s1rw = (const float*)d_in[10];
    const float* s2lw = (const float*)d_in[11];
    const float* s2lb = (const float*)d_in[12];
    const float* s2rw = (const float*)d_in[13];
    float* out = (float*)d_out;

    cudaFuncSetAttribute(conv2_mma, cudaFuncAttributeMaxDynamicSharedMemorySize,
                         C2_SMEM);
    cudaFuncSetAttribute(fc_kernel, cudaFuncAttributeMaxDynamicSharedMemorySize,
                         FC_SMEM_BYTES);

    prep_all<<<672, 256>>>(c2w, s1lw, s1rw, s2lw, s2rw);
    conv1_kernel<<<1024, 256>>>(x, c1w, c1b);
    conv2_mma<<<1024, 512, C2_SMEM>>>(c2b);
    fc_kernel<<<128, 256, FC_SMEM_BYTES>>>(fcw, fcb, mask);
    sage_kernel<256, true, true><<<dim3(32, 4), 256>>>(s1lb, out);
    sage_kernel<128, false, false><<<dim3(32, 4), 256>>>(s2lb, out);
}

// round 16
// speedup vs baseline: 1.0118x; 1.0037x over previous
#include <cuda_runtime.h>
#include <cuda_fp16.h>
#include <cstdint>

// ===========================================================================
// GraphSageNet GB300 — round 15.
// Exact R12 (proven 698.5us) with two deltas:
//  1) prep_all folded into conv1 entry (one fewer launch; each of conv1's
//     262144 threads does <=1 prep element; consumers run in later kernels).
//  2) sage weight loops keep #pragma unroll (MLP for L2 stream).
// conv1 body frozen at 256thr/8oc x 8px, NO launch_bounds minCTAs (R9/R13/R14
// all proved any occupancy push spills its ~150-reg live set).
// ===========================================================================

#define NPAD 1280
#define GUARD 64
#define ROWS_TOTAL (GUARD + 1024 * NPAD + GUARD)

__device__ __align__(16) __half g_act[(size_t)ROWS_TOTAL * 64];
__device__ __align__(16) __half g_wh[2 * 9 * 4096];
__device__ __align__(16) float g_pp[1024 * 128];
__device__ __align__(16) float g_h1[1024 * 256];
__device__ __align__(16) float g_h2[1024 * 256];
__device__ __align__(16) float g_w21t[256 * 256];
__device__ __align__(16) float g_l1t [256 * 256];
__device__ __align__(16) float g_w22t[256 * 128];
__device__ __align__(16) float g_l2t [256 * 128];

// ------------------------------- helpers -----------------------------------
__device__ __forceinline__ uint32_t smem_u32(const void* p) {
    uint32_t a;
    asm("{ .reg .u64 t; cvta.to.shared.u64 t, %1; cvt.u32.u64 %0, t; }"
        : "=r"(a) : "l"(p));
    return a;
}
__device__ __forceinline__ void ldsm4(uint32_t* r, uint32_t addr) {
    asm volatile("ldmatrix.sync.aligned.m8n8.x4.shared.b16 {%0,%1,%2,%3}, [%4];"
                 : "=r"(r[0]), "=r"(r[1]), "=r"(r[2]), "=r"(r[3]) : "r"(addr));
}
__device__ __forceinline__ void mma16816(float* d, const uint32_t* a,
                                         uint32_t b0, uint32_t b1) {
    asm volatile(
        "mma.sync.aligned.m16n8k16.row.col.f32.f16.f16.f32 "
        "{%0,%1,%2,%3}, {%4,%5,%6,%7}, {%8,%9}, {%0,%1,%2,%3};"
        : "+f"(d[0]), "+f"(d[1]), "+f"(d[2]), "+f"(d[3])
        : "r"(a[0]), "r"(a[1]), "r"(a[2]), "r"(a[3]), "r"(b0), "r"(b1));
}
#define CPA16(dst, src) \
    asm volatile("cp.async.cg.shared.global [%0], [%1], 16;" \
                 :: "r"(dst), "l"(src) : "memory")
#define CPA_COMMIT() asm volatile("cp.async.commit_group;" ::: "memory")

__device__ __forceinline__ unsigned long long pack2(float lo, float hi) {
    unsigned long long d;
    asm("mov.b64 %0, {%1, %2};" : "=l"(d)
        : "r"(__float_as_uint(lo)), "r"(__float_as_uint(hi)));
    return d;
}
__device__ __forceinline__ void unpack2(unsigned long long v, float& lo, float& hi) {
    unsigned a, b;
    asm("mov.b64 {%0, %1}, %2;" : "=r"(a), "=r"(b) : "l"(v));
    lo = __uint_as_float(a); hi = __uint_as_float(b);
}
__device__ __forceinline__ void fma2(unsigned long long& d, unsigned long long a,
                                     unsigned long long b, unsigned long long c) {
    asm("fma.rn.f32x2 %0, %1, %2, %3;" : "=l"(d) : "l"(a), "l"(b), "l"(c));
}

// ---------------------------------------------------------------------------
// conv1 (+ folded prep): [1024,3,32,32] -> relu -> fp16 padded px-major.
// Each thread first handles <=1 prep element (conv2 weight swizzle / sage
// weight fold), then its conv work. 256 thr, 8oc x 8px (frozen config).
// ---------------------------------------------------------------------------
__global__ void __launch_bounds__(256) conv1_kernel(
    const float* __restrict__ x, const float* __restrict__ w,
    const float* __restrict__ b,
    const float* __restrict__ c2w,
    const float* __restrict__ s1lw, const float* __restrict__ s1rw,
    const float* __restrict__ s2lw, const float* __restrict__ s2rw) {
    __shared__ __align__(16) float ws[27 * 64];
    __shared__ __align__(16) float xs[3 * 34 * 35];

    const int n = blockIdx.x, tid = threadIdx.x;

    // ---- folded prep: global thread id -> one prep element ----
    {
        const float C = 1.f / 31.f;
        int idx = n * 256 + tid;
        if (idx < 73728) {
            int s = idx % 9, t = idx / 9;
            int ic = t % 64, oc = t / 64;
            float v = c2w[oc * 576 + ic * 9 + s];
            int ocg = oc >> 6, ocl = oc & 63;
            uint32_t off = (uint32_t)(ocl * 128 + ic * 2);
            uint32_t sw = off ^ ((off >> 3) & 0x70);
            uint32_t base = ((uint32_t)ocg * 9 + (uint32_t)s) * 8192u;
            *(__half*)((char*)g_wh + base + sw) = __float2half_rn(v);
        } else if (idx < 73728 + 65536) {
            int j = idx - 73728;
            int o = j >> 8, d = j & 255;
            float l = s1lw[j];
            g_w21t[d * 256 + o] = s1rw[j] - C * l;
            g_l1t [d * 256 + o] = l;
        } else if (idx < 73728 + 98304) {
            int j2 = idx - 73728 - 65536;
            int o = j2 >> 8, d = j2 & 255;
            float l = s2lw[j2];
            g_w22t[d * 128 + o] = s2rw[j2] - C * l;
            g_l2t [d * 128 + o] = l;
        }
    }

    for (int i = tid; i < 3 * 34 * 35; i += 256) xs[i] = 0.f;
    for (int i = tid; i < 64 * 27; i += 256) {
        int oc = i / 27, k = i % 27;
        ws[k * 64 + oc] = w[i];
    }
    __syncthreads();
    const float* xin = x + n * 3072;
    for (int i = tid; i < 3072; i += 256) {
        int ic = i >> 10, r = (i >> 5) & 31, c = i & 31;
        xs[ic * (34 * 35) + (r + 1) * 35 + (c + 1)] = xin[i];
    }
    __syncthreads();

    const int ocq = tid >> 5, oc0 = ocq * 8;
    unsigned long long bp[8];
#pragma unroll
    for (int j = 0; j < 8; j++) {
        float bv = b[oc0 + j];
        bp[j] = pack2(bv, bv);
    }

    for (int it = 0; it < 4; it++) {
        int pg = it * 32 + (tid & 31);
        int row = pg >> 2, colb = (pg & 3) * 8;
        unsigned long long acc[8][4];
#pragma unroll
        for (int j = 0; j < 8; j++)
#pragma unroll
            for (int t = 0; t < 4; t++) acc[j][t] = bp[j];

#pragma unroll
        for (int ic = 0; ic < 3; ic++)
#pragma unroll
            for (int kr = 0; kr < 3; kr++) {
                int base = ic * (34 * 35) + (row + kr) * 35 + colb;
                float in10[10];
#pragma unroll
                for (int q = 0; q < 10; q++) in10[q] = xs[base + q];
#pragma unroll
                for (int kc = 0; kc < 3; kc++) {
                    int k = ic * 9 + kr * 3 + kc;
                    float4 w0 = *(const float4*)&ws[k * 64 + oc0];
                    float4 w1 = *(const float4*)&ws[k * 64 + oc0 + 4];
                    float wv[8] = {w0.x, w0.y, w0.z, w0.w, w1.x, w1.y, w1.z, w1.w};
                    unsigned long long ip[4];
#pragma unroll
                    for (int t = 0; t < 4; t++)
                        ip[t] = pack2(in10[kc + 2 * t], in10[kc + 2 * t + 1]);
#pragma unroll
                    for (int j = 0; j < 8; j++) {
                        unsigned long long wp = pack2(wv[j], wv[j]);
#pragma unroll
                        for (int t = 0; t < 4; t++) fma2(acc[j][t], wp, ip[t], acc[j][t]);
                    }
                }
            }
#pragma unroll
        for (int p = 0; p < 8; p++) {
            int col = colb + p;
            size_t pxa = (size_t)GUARD + (size_t)n * NPAD + (row + 1) * 34 + (col + 1);
            uint32_t q[4];
#pragma unroll
            for (int pr = 0; pr < 4; pr++) {
                float a0l, a0h, a1l, a1h;
                unpack2(acc[2 * pr][p >> 1], a0l, a0h);
                unpack2(acc[2 * pr + 1][p >> 1], a1l, a1h);
                float v0 = (p & 1) ? a0h : a0l;
                float v1 = (p & 1) ? a1h : a1l;
                __half h0 = __float2half_rn(fmaxf(v0, 0.f));
                __half h1 = __float2half_rn(fmaxf(v1, 0.f));
                q[pr] = (uint32_t)__half_as_ushort(h0) |
                        ((uint32_t)__half_as_ushort(h1) << 16);
            }
            *(uint4*)&g_act[pxa * 64 + oc0] = make_uint4(q[0], q[1], q[2], q[3]);
        }
    }
}

// ---------------------------------------------------------------------------
// conv2 (R10/R12 proven): grid 1024, 512 thr, triple-buffered slab ring.
// ---------------------------------------------------------------------------
#define SM_WH 0
#define SM_SLAB 147456
#define SLAB_BYTES 25344
#define SM_BIAS (SM_SLAB + 3 * SLAB_BYTES)
#define SM_RED (SM_BIAS + 512)
#define C2_SMEM (SM_RED + 2048)

__device__ __forceinline__ void stage_slab(uint32_t sbase, const uint4* src, int tid) {
    for (int i = tid; i < 1584; i += 512) {
        int r = i >> 3, j = i & 7;
        uint32_t d = (uint32_t)(r * 128) +
                     (((uint32_t)(j * 16)) ^ ((uint32_t)((r & 7) << 4)));
        CPA16(sbase + d, src + (size_t)r * 8 + j);
    }
}

__global__ void __launch_bounds__(512, 1) conv2_mma(const float* __restrict__ bias) {
    extern __shared__ __align__(1024) char smc[];
    const uint32_t smb = smem_u32(smc);
    const int tid = threadIdx.x, wid = tid >> 5, lane = tid & 31;
    const int n = blockIdx.x;
    const int pxw = wid & 3, ocw = wid >> 2;

    const size_t img_base = (size_t)GUARD + (size_t)n * NPAD;
    const uint4* slab0 = (const uint4*)g_act + (img_base - 35) * 8;

    {
        const uint4* srcH = (const uint4*)g_wh;
        for (int i = tid; i < 9216; i += 512)
            CPA16(smb + SM_WH + i * 16, srcH + i);
        stage_slab(smb + SM_SLAB, slab0, tid);
        CPA_COMMIT();
        stage_slab(smb + SM_SLAB + SLAB_BYTES, slab0 + 1024, tid);
        CPA_COMMIT();
    }
    if (tid < 128) ((float*)(smc + SM_BIAS))[tid] = bias[tid];

    const int l15 = lane & 15;
    const uint32_t lk = (uint32_t)((lane >> 4) * 16);
    const uint32_t wgBase = (uint32_t)((ocw >> 1) * 9) * 8192u;
    const int rB0 = (ocw & 1) * 32 + l15, rB1 = rB0 + 16;
    const uint32_t swB0 = (uint32_t)((rB0 & 7) << 4);
    const uint32_t swB1 = (uint32_t)((rB1 & 7) << 4);

    float b8[8];
#pragma unroll
    for (int nt = 0; nt < 4; nt++)
#pragma unroll
        for (int bb = 0; bb < 2; bb++)
            b8[nt * 2 + bb] = bias[ocw * 32 + nt * 8 + (lane & 3) * 2 + bb];

    float psum[8];
#pragma unroll
    for (int i = 0; i < 8; i++) psum[i] = 0.f;

    for (int t = 0; t < 9; t++) {
        if (t < 8) {
            asm volatile("cp.async.wait_group 1;" ::: "memory");
        } else {
            asm volatile("cp.async.wait_group 0;" ::: "memory");
        }
        __syncthreads();
        if (t < 7) {
            stage_slab(smb + SM_SLAB + (uint32_t)(((t + 2) % 3) * SLAB_BYTES),
                       slab0 + (size_t)(t + 2) * 1024, tid);
            CPA_COMMIT();
        }

        const uint32_t sbA = smb + SM_SLAB + (uint32_t)((t % 3) * SLAB_BYTES);
        float acc[2][4][4];
#pragma unroll
        for (int mt = 0; mt < 2; mt++)
#pragma unroll
            for (int nt = 0; nt < 4; nt++)
#pragma unroll
                for (int rg = 0; rg < 4; rg++) acc[mt][nt][rg] = 0.f;

#pragma unroll
        for (int s = 0; s < 9; s++) {
            const int doff = (s / 3 - 1) * 34 + (s % 3 - 1);
            const int rA0 = 35 + doff + pxw * 32 + l15;
            const int rA1 = rA0 + 16;
            const uint32_t swA0 = (uint32_t)((rA0 & 7) << 4);
            const uint32_t swA1 = (uint32_t)((rA1 & 7) << 4);
            const uint32_t wt = wgBase + (uint32_t)(s * 8192);
#pragma unroll
            for (int k = 0; k < 4; k++) {
                const uint32_t kb = (uint32_t)(k * 32) + lk;
                uint32_t a0[4], a1[4], bh0[4], bh1[4];
                ldsm4(a0, sbA + (uint32_t)(rA0 * 128) + (kb ^ swA0));
                ldsm4(a1, sbA + (uint32_t)(rA1 * 128) + (kb ^ swA1));
                ldsm4(bh0, smb + SM_WH + wt + (uint32_t)(rB0 * 128) + (kb ^ swB0));
                ldsm4(bh1, smb + SM_WH + wt + (uint32_t)(rB1 * 128) + (kb ^ swB1));
                mma16816(acc[0][0], a0, bh0[0], bh0[2]);
                mma16816(acc[0][1], a0, bh0[1], bh0[3]);
                mma16816(acc[0][2], a0, bh1[0], bh1[2]);
                mma16816(acc[0][3], a0, bh1[1], bh1[3]);
                mma16816(acc[1][0], a1, bh0[0], bh0[2]);
                mma16816(acc[1][1], a1, bh0[1], bh0[3]);
                mma16816(acc[1][2], a1, bh1[0], bh1[2]);
                mma16816(acc[1][3], a1, bh1[1], bh1[3]);
            }
        }

        bool inter[2][2];
#pragma unroll
        for (int mt = 0; mt < 2; mt++)
#pragma unroll
            for (int hh = 0; hh < 2; hh++) {
                int pl = t * 128 + pxw * 32 + mt * 16 + (lane >> 2) + hh * 8;
                int rr = pl / 34, cc = pl - rr * 34;
                inter[mt][hh] =
                    (pl < 1156) & (rr >= 1) & (rr <= 32) & (cc >= 1) & (cc <= 32);
            }
#pragma unroll
        for (int mt = 0; mt < 2; mt++)
#pragma unroll
            for (int nt = 0; nt < 4; nt++)
#pragma unroll
                for (int rg = 0; rg < 4; rg++) {
                    float v = fmaxf(acc[mt][nt][rg] + b8[nt * 2 + (rg & 1)], 0.f);
                    if (inter[mt][rg >> 1]) psum[nt * 2 + (rg & 1)] += v;
                }
    }

#pragma unroll
    for (int off = 4; off <= 16; off <<= 1)
#pragma unroll
        for (int i = 0; i < 8; i++)
            psum[i] += __shfl_xor_sync(0xffffffffu, psum[i], off);

    float* red = (float*)(smc + SM_RED);
    if (lane < 4) {
#pragma unroll
        for (int nt = 0; nt < 4; nt++)
#pragma unroll
            for (int bb = 0; bb < 2; bb++)
                red[wid * 32 + nt * 8 + lane * 2 + bb] = psum[nt * 2 + bb];
    }
    __syncthreads();
    if (tid < 128) {
        int og = tid >> 5, c = tid & 31;
        float s = 0.f;
#pragma unroll
        for (int p = 0; p < 4; p++) s += red[(og * 4 + p) * 32 + c];
        g_pp[n * 128 + og * 32 + c] = s;
    }
}

// ---------------------------------------------------------------------------
// fc: (g_pp/1024) [1024,128] @ fc_w.T + fc_b, * mask -> g_h1 (proven 26us)
// ---------------------------------------------------------------------------
#define FC_SMEM_BYTES ((128 * 256 + 8 * 128) * 4)

__global__ void __launch_bounds__(256) fc_kernel(const float* __restrict__ fcw,
                                                 const float* __restrict__ fcb,
                                                 const float* __restrict__ mask) {
    extern __shared__ __align__(16) float smf[];
    float* ws = smf;
    float* ps = smf + 128 * 256;
    const int row0 = blockIdx.x * 8, tid = threadIdx.x;

    for (int i = tid; i < 128 * 256; i += 256) {
        int o = i >> 7, d = i & 127;
        ws[d * 256 + o] = fcw[i];
    }
    for (int i = tid; i < 8 * 128; i += 256)
        ps[i] = g_pp[row0 * 128 + i] * (1.f / 1024.f);
    __syncthreads();

    const int o = tid;
    float acc[8];
    float bb = fcb[o];
#pragma unroll
    for (int rr = 0; rr < 8; rr++) acc[rr] = bb;
    for (int d = 0; d < 128; d++) {
        float wv = ws[d * 256 + o];
#pragma unroll
        for (int rr = 0; rr < 8; rr++) acc[rr] = fmaf(ps[rr * 128 + d], wv, acc[rr]);
    }
#pragma unroll
    for (int rr = 0; rr < 8; rr++) {
        int row = row0 + rr;
        g_h1[row * 256 + o] = acc[rr] * mask[row];
    }
}

// ---------------------------------------------------------------------------
// SAGE layer, folded weights: out = h @ W2^T + [cs @ lw^T / 31 + lb]
// grid (32 b, 4 segs of 8 nodes); weight loops unrolled for MLP.
// ---------------------------------------------------------------------------
template <int OUTD, bool RELU, bool FROM_H1>
__global__ void __launch_bounds__(256) sage_kernel(const float* __restrict__ lb,
                                                   float* __restrict__ out) {
    __shared__ __align__(16) float hs[32 * 260];
    __shared__ float CS[256];
    const int b = blockIdx.x, tid = threadIdx.x;
    const int n0 = blockIdx.y * 8;
    const float* hb = (FROM_H1 ? g_h1 : g_h2) + b * 8192;

    for (int i = tid; i < 8192; i += 256) {
        int nn = i >> 8, d = i & 255;
        hs[nn * 260 + d] = hb[i];
    }
    __syncthreads();
    {
        const int d = tid;
        float s = 0.f;
#pragma unroll
        for (int nn = 0; nn < 32; nn++) s += hs[nn * 260 + d];
        CS[d] = s;
    }
    __syncthreads();

    const float* lt = (OUTD == 256) ? g_l1t : g_l2t;
    const float* wt = (OUTD == 256) ? g_w21t : g_w22t;
    const int o = tid;
    if (o < OUTD) {
        float v = 0.f;
#pragma unroll 4
        for (int d = 0; d < 256; d += 4)
            v += CS[d] * lt[d * OUTD + o] + CS[d + 1] * lt[(d + 1) * OUTD + o] +
                 CS[d + 2] * lt[(d + 2) * OUTD + o] +
                 CS[d + 3] * lt[(d + 3) * OUTD + o];
        float init = v * (1.f / 31.f) + lb[o];
        float acc[8];
#pragma unroll
        for (int nn = 0; nn < 8; nn++) acc[nn] = init;
#pragma unroll 8
        for (int d = 0; d < 256; d++) {
            float w = wt[d * OUTD + o];
#pragma unroll
            for (int nn = 0; nn < 8; nn++)
                acc[nn] = fmaf(hs[(n0 + nn) * 260 + d], w, acc[nn]);
        }
#pragma unroll
        for (int nn = 0; nn < 8; nn++) {
            float r = acc[nn];
            if (RELU) r = fmaxf(r, 0.f);
            if (OUTD == 256)
                g_h2[(b * 32 + n0 + nn) * 256 + o] = r;
            else
                out[(b * 32 + n0 + nn) * OUTD + o] = r;
        }
    }
}

// ---------------------------------------------------------------------------
extern "C" void kernel_launch(void* const* d_in, const int* in_sizes, int n_in,
                              void* d_out, int out_size) {
    const float* x    = (const float*)d_in[0];
    const float* mask = (const float*)d_in[1];
    const float* c1w  = (const float*)d_in[2];
    const float* c1b  = (const float*)d_in[3];
    const float* c2w  = (const float*)d_in[4];
    const float* c2b  = (const float*)d_in[5];
    const float* fcw  = (const float*)d_in[6];
    const float* fcb  = (const float*)d_in[7];
    const float* s1lw = (const float*)d_in[8];
    const float* s1lb = (const float*)d_in[9];
    const float* s1rw = (const float*)d_in[10];
    const float* s2lw = (const float*)d_in[11];
    const float* s2lb = (const float*)d_in[12];
    const float* s2rw = (const float*)d_in[13];
    float* out = (float*)d_out;

    cudaFuncSetAttribute(conv2_mma, cudaFuncAttributeMaxDynamicSharedMemorySize,
                         C2_SMEM);
    cudaFuncSetAttribute(fc_kernel, cudaFuncAttributeMaxDynamicSharedMemorySize,
                         FC_SMEM_BYTES);

    conv1_kernel<<<1024, 256>>>(x, c1w, c1b, c2w, s1lw, s1rw, s2lw, s2rw);
    conv2_mma<<<1024, 512, C2_SMEM>>>(c2b);
    fc_kernel<<<128, 256, FC_SMEM_BYTES>>>(fcw, fcb, mask);
    sage_kernel<256, true, true><<<dim3(32, 4), 256>>>(s1lb, out);
    sage_kernel<128, false, false><<<dim3(32, 4), 256>>>(s2lb, out);
}

// round 17
// speedup vs baseline: 1.0586x; 1.0462x over previous
#include <cuda_runtime.h>
#include <cuda_fp16.h>
#include <cstdint>

// ===========================================================================
// GraphSageNet GB300 — round 16.
// Base: exact R12 (proven 698.5us): separate prep_all, unroll-free loops,
//       frozen conv1 (256thr/8oc), frozen conv2 (RF-bound), fc.
// NEW:  sage kernels redesigned — 512 threads, d-reduction SPLIT across
//       512/OUTD thread groups (2x for sage1, 4x for sage2) to cut the
//       serial global-load chain (measured: sage1 latency-bound, issue 9.3%).
//       Partials combined once via smem. fp32 reassociation only.
// ===========================================================================

#define NPAD 1280
#define GUARD 64
#define ROWS_TOTAL (GUARD + 1024 * NPAD + GUARD)

__device__ __align__(16) __half g_act[(size_t)ROWS_TOTAL * 64];
__device__ __align__(16) __half g_wh[2 * 9 * 4096];
__device__ __align__(16) float g_pp[1024 * 128];
__device__ __align__(16) float g_h1[1024 * 256];
__device__ __align__(16) float g_h2[1024 * 256];
__device__ __align__(16) float g_w21t[256 * 256];
__device__ __align__(16) float g_l1t [256 * 256];
__device__ __align__(16) float g_w22t[256 * 128];
__device__ __align__(16) float g_l2t [256 * 128];

// ------------------------------- helpers -----------------------------------
__device__ __forceinline__ uint32_t smem_u32(const void* p) {
    uint32_t a;
    asm("{ .reg .u64 t; cvta.to.shared.u64 t, %1; cvt.u32.u64 %0, t; }"
        : "=r"(a) : "l"(p));
    return a;
}
__device__ __forceinline__ void ldsm4(uint32_t* r, uint32_t addr) {
    asm volatile("ldmatrix.sync.aligned.m8n8.x4.shared.b16 {%0,%1,%2,%3}, [%4];"
                 : "=r"(r[0]), "=r"(r[1]), "=r"(r[2]), "=r"(r[3]) : "r"(addr));
}
__device__ __forceinline__ void mma16816(float* d, const uint32_t* a,
                                         uint32_t b0, uint32_t b1) {
    asm volatile(
        "mma.sync.aligned.m16n8k16.row.col.f32.f16.f16.f32 "
        "{%0,%1,%2,%3}, {%4,%5,%6,%7}, {%8,%9}, {%0,%1,%2,%3};"
        : "+f"(d[0]), "+f"(d[1]), "+f"(d[2]), "+f"(d[3])
        : "r"(a[0]), "r"(a[1]), "r"(a[2]), "r"(a[3]), "r"(b0), "r"(b1));
}
#define CPA16(dst, src) \
    asm volatile("cp.async.cg.shared.global [%0], [%1], 16;" \
                 :: "r"(dst), "l"(src) : "memory")
#define CPA_COMMIT() asm volatile("cp.async.commit_group;" ::: "memory")

__device__ __forceinline__ unsigned long long pack2(float lo, float hi) {
    unsigned long long d;
    asm("mov.b64 %0, {%1, %2};" : "=l"(d)
        : "r"(__float_as_uint(lo)), "r"(__float_as_uint(hi)));
    return d;
}
__device__ __forceinline__ void unpack2(unsigned long long v, float& lo, float& hi) {
    unsigned a, b;
    asm("mov.b64 {%0, %1}, %2;" : "=r"(a), "=r"(b) : "l"(v));
    lo = __uint_as_float(a); hi = __uint_as_float(b);
}
__device__ __forceinline__ void fma2(unsigned long long& d, unsigned long long a,
                                     unsigned long long b, unsigned long long c) {
    asm("fma.rn.f32x2 %0, %1, %2, %3;" : "=l"(d) : "l"(a), "l"(b), "l"(c));
}

// ---------------------------------------------------------------------------
// prep_all: conv2 weights -> fp16 SW128 tiles; sage folded weights
// ---------------------------------------------------------------------------
__global__ void prep_all(const float* __restrict__ w,
                         const float* __restrict__ s1lw,
                         const float* __restrict__ s1rw,
                         const float* __restrict__ s2lw,
                         const float* __restrict__ s2rw) {
    const float C = 1.f / 31.f;
    int idx = blockIdx.x * 256 + threadIdx.x;
    if (idx < 73728) {
        int s = idx % 9, t = idx / 9;
        int ic = t % 64, oc = t / 64;
        float v = w[oc * 576 + ic * 9 + s];
        int ocg = oc >> 6, ocl = oc & 63;
        uint32_t off = (uint32_t)(ocl * 128 + ic * 2);
        uint32_t sw = off ^ ((off >> 3) & 0x70);
        uint32_t base = ((uint32_t)ocg * 9 + (uint32_t)s) * 8192u;
        *(__half*)((char*)g_wh + base + sw) = __float2half_rn(v);
    } else {
        int j = idx - 73728;
        if (j < 65536) {
            int o = j >> 8, d = j & 255;
            float l = s1lw[j];
            g_w21t[d * 256 + o] = s1rw[j] - C * l;
            g_l1t [d * 256 + o] = l;
        } else if (j < 98304) {
            int j2 = j - 65536;
            int o = j2 >> 8, d = j2 & 255;
            float l = s2lw[j2];
            g_w22t[d * 128 + o] = s2rw[j2] - C * l;
            g_l2t [d * 128 + o] = l;
        }
    }
}

// ---------------------------------------------------------------------------
// conv1 (R12 frozen): [1024,3,32,32] -> relu -> fp16 padded px-major; f32x2.
// ---------------------------------------------------------------------------
__global__ void __launch_bounds__(256) conv1_kernel(const float* __restrict__ x,
                                                    const float* __restrict__ w,
                                                    const float* __restrict__ b) {
    __shared__ __align__(16) float ws[27 * 64];
    __shared__ __align__(16) float xs[3 * 34 * 35];

    const int n = blockIdx.x, tid = threadIdx.x;

    for (int i = tid; i < 3 * 34 * 35; i += 256) xs[i] = 0.f;
    for (int i = tid; i < 64 * 27; i += 256) {
        int oc = i / 27, k = i % 27;
        ws[k * 64 + oc] = w[i];
    }
    __syncthreads();
    const float* xin = x + n * 3072;
    for (int i = tid; i < 3072; i += 256) {
        int ic = i >> 10, r = (i >> 5) & 31, c = i & 31;
        xs[ic * (34 * 35) + (r + 1) * 35 + (c + 1)] = xin[i];
    }
    __syncthreads();

    const int ocq = tid >> 5, oc0 = ocq * 8;
    unsigned long long bp[8];
#pragma unroll
    for (int j = 0; j < 8; j++) {
        float bv = b[oc0 + j];
        bp[j] = pack2(bv, bv);
    }

    for (int it = 0; it < 4; it++) {
        int pg = it * 32 + (tid & 31);
        int row = pg >> 2, colb = (pg & 3) * 8;
        unsigned long long acc[8][4];
#pragma unroll
        for (int j = 0; j < 8; j++)
#pragma unroll
            for (int t = 0; t < 4; t++) acc[j][t] = bp[j];

#pragma unroll
        for (int ic = 0; ic < 3; ic++)
#pragma unroll
            for (int kr = 0; kr < 3; kr++) {
                int base = ic * (34 * 35) + (row + kr) * 35 + colb;
                float in10[10];
#pragma unroll
                for (int q = 0; q < 10; q++) in10[q] = xs[base + q];
#pragma unroll
                for (int kc = 0; kc < 3; kc++) {
                    int k = ic * 9 + kr * 3 + kc;
                    float4 w0 = *(const float4*)&ws[k * 64 + oc0];
                    float4 w1 = *(const float4*)&ws[k * 64 + oc0 + 4];
                    float wv[8] = {w0.x, w0.y, w0.z, w0.w, w1.x, w1.y, w1.z, w1.w};
                    unsigned long long ip[4];
#pragma unroll
                    for (int t = 0; t < 4; t++)
                        ip[t] = pack2(in10[kc + 2 * t], in10[kc + 2 * t + 1]);
#pragma unroll
                    for (int j = 0; j < 8; j++) {
                        unsigned long long wp = pack2(wv[j], wv[j]);
#pragma unroll
                        for (int t = 0; t < 4; t++) fma2(acc[j][t], wp, ip[t], acc[j][t]);
                    }
                }
            }
#pragma unroll
        for (int p = 0; p < 8; p++) {
            int col = colb + p;
            size_t pxa = (size_t)GUARD + (size_t)n * NPAD + (row + 1) * 34 + (col + 1);
            uint32_t q[4];
#pragma unroll
            for (int pr = 0; pr < 4; pr++) {
                float a0l, a0h, a1l, a1h;
                unpack2(acc[2 * pr][p >> 1], a0l, a0h);
                unpack2(acc[2 * pr + 1][p >> 1], a1l, a1h);
                float v0 = (p & 1) ? a0h : a0l;
                float v1 = (p & 1) ? a1h : a1l;
                __half h0 = __float2half_rn(fmaxf(v0, 0.f));
                __half h1 = __float2half_rn(fmaxf(v1, 0.f));
                q[pr] = (uint32_t)__half_as_ushort(h0) |
                        ((uint32_t)__half_as_ushort(h1) << 16);
            }
            *(uint4*)&g_act[pxa * 64 + oc0] = make_uint4(q[0], q[1], q[2], q[3]);
        }
    }
}

// ---------------------------------------------------------------------------
// conv2 (R12 frozen): grid 1024, 512 thr, triple-buffered slab ring.
// ---------------------------------------------------------------------------
#define SM_WH 0
#define SM_SLAB 147456
#define SLAB_BYTES 25344
#define SM_BIAS (SM_SLAB + 3 * SLAB_BYTES)
#define SM_RED (SM_BIAS + 512)
#define C2_SMEM (SM_RED + 2048)

__device__ __forceinline__ void stage_slab(uint32_t sbase, const uint4* src, int tid) {
    for (int i = tid; i < 1584; i += 512) {
        int r = i >> 3, j = i & 7;
        uint32_t d = (uint32_t)(r * 128) +
                     (((uint32_t)(j * 16)) ^ ((uint32_t)((r & 7) << 4)));
        CPA16(sbase + d, src + (size_t)r * 8 + j);
    }
}

__global__ void __launch_bounds__(512, 1) conv2_mma(const float* __restrict__ bias) {
    extern __shared__ __align__(1024) char smc[];
    const uint32_t smb = smem_u32(smc);
    const int tid = threadIdx.x, wid = tid >> 5, lane = tid & 31;
    const int n = blockIdx.x;
    const int pxw = wid & 3, ocw = wid >> 2;

    const size_t img_base = (size_t)GUARD + (size_t)n * NPAD;
    const uint4* slab0 = (const uint4*)g_act + (img_base - 35) * 8;

    {
        const uint4* srcH = (const uint4*)g_wh;
        for (int i = tid; i < 9216; i += 512)
            CPA16(smb + SM_WH + i * 16, srcH + i);
        stage_slab(smb + SM_SLAB, slab0, tid);
        CPA_COMMIT();
        stage_slab(smb + SM_SLAB + SLAB_BYTES, slab0 + 1024, tid);
        CPA_COMMIT();
    }
    if (tid < 128) ((float*)(smc + SM_BIAS))[tid] = bias[tid];

    const int l15 = lane & 15;
    const uint32_t lk = (uint32_t)((lane >> 4) * 16);
    const uint32_t wgBase = (uint32_t)((ocw >> 1) * 9) * 8192u;
    const int rB0 = (ocw & 1) * 32 + l15, rB1 = rB0 + 16;
    const uint32_t swB0 = (uint32_t)((rB0 & 7) << 4);
    const uint32_t swB1 = (uint32_t)((rB1 & 7) << 4);

    float b8[8];
#pragma unroll
    for (int nt = 0; nt < 4; nt++)
#pragma unroll
        for (int bb = 0; bb < 2; bb++)
            b8[nt * 2 + bb] = bias[ocw * 32 + nt * 8 + (lane & 3) * 2 + bb];

    float psum[8];
#pragma unroll
    for (int i = 0; i < 8; i++) psum[i] = 0.f;

    for (int t = 0; t < 9; t++) {
        if (t < 8) {
            asm volatile("cp.async.wait_group 1;" ::: "memory");
        } else {
            asm volatile("cp.async.wait_group 0;" ::: "memory");
        }
        __syncthreads();
        if (t < 7) {
            stage_slab(smb + SM_SLAB + (uint32_t)(((t + 2) % 3) * SLAB_BYTES),
                       slab0 + (size_t)(t + 2) * 1024, tid);
            CPA_COMMIT();
        }

        const uint32_t sbA = smb + SM_SLAB + (uint32_t)((t % 3) * SLAB_BYTES);
        float acc[2][4][4];
#pragma unroll
        for (int mt = 0; mt < 2; mt++)
#pragma unroll
            for (int nt = 0; nt < 4; nt++)
#pragma unroll
                for (int rg = 0; rg < 4; rg++) acc[mt][nt][rg] = 0.f;

#pragma unroll
        for (int s = 0; s < 9; s++) {
            const int doff = (s / 3 - 1) * 34 + (s % 3 - 1);
            const int rA0 = 35 + doff + pxw * 32 + l15;
            const int rA1 = rA0 + 16;
            const uint32_t swA0 = (uint32_t)((rA0 & 7) << 4);
            const uint32_t swA1 = (uint32_t)((rA1 & 7) << 4);
            const uint32_t wt = wgBase + (uint32_t)(s * 8192);
#pragma unroll
            for (int k = 0; k < 4; k++) {
                const uint32_t kb = (uint32_t)(k * 32) + lk;
                uint32_t a0[4], a1[4], bh0[4], bh1[4];
                ldsm4(a0, sbA + (uint32_t)(rA0 * 128) + (kb ^ swA0));
                ldsm4(a1, sbA + (uint32_t)(rA1 * 128) + (kb ^ swA1));
                ldsm4(bh0, smb + SM_WH + wt + (uint32_t)(rB0 * 128) + (kb ^ swB0));
                ldsm4(bh1, smb + SM_WH + wt + (uint32_t)(rB1 * 128) + (kb ^ swB1));
                mma16816(acc[0][0], a0, bh0[0], bh0[2]);
                mma16816(acc[0][1], a0, bh0[1], bh0[3]);
                mma16816(acc[0][2], a0, bh1[0], bh1[2]);
                mma16816(acc[0][3], a0, bh1[1], bh1[3]);
                mma16816(acc[1][0], a1, bh0[0], bh0[2]);
                mma16816(acc[1][1], a1, bh0[1], bh0[3]);
                mma16816(acc[1][2], a1, bh1[0], bh1[2]);
                mma16816(acc[1][3], a1, bh1[1], bh1[3]);
            }
        }

        bool inter[2][2];
#pragma unroll
        for (int mt = 0; mt < 2; mt++)
#pragma unroll
            for (int hh = 0; hh < 2; hh++) {
                int pl = t * 128 + pxw * 32 + mt * 16 + (lane >> 2) + hh * 8;
                int rr = pl / 34, cc = pl - rr * 34;
                inter[mt][hh] =
                    (pl < 1156) & (rr >= 1) & (rr <= 32) & (cc >= 1) & (cc <= 32);
            }
#pragma unroll
        for (int mt = 0; mt < 2; mt++)
#pragma unroll
            for (int nt = 0; nt < 4; nt++)
#pragma unroll
                for (int rg = 0; rg < 4; rg++) {
                    float v = fmaxf(acc[mt][nt][rg] + b8[nt * 2 + (rg & 1)], 0.f);
                    if (inter[mt][rg >> 1]) psum[nt * 2 + (rg & 1)] += v;
                }
    }

#pragma unroll
    for (int off = 4; off <= 16; off <<= 1)
#pragma unroll
        for (int i = 0; i < 8; i++)
            psum[i] += __shfl_xor_sync(0xffffffffu, psum[i], off);

    float* red = (float*)(smc + SM_RED);
    if (lane < 4) {
#pragma unroll
        for (int nt = 0; nt < 4; nt++)
#pragma unroll
            for (int bb = 0; bb < 2; bb++)
                red[wid * 32 + nt * 8 + lane * 2 + bb] = psum[nt * 2 + bb];
    }
    __syncthreads();
    if (tid < 128) {
        int og = tid >> 5, c = tid & 31;
        float s = 0.f;
#pragma unroll
        for (int p = 0; p < 4; p++) s += red[(og * 4 + p) * 32 + c];
        g_pp[n * 128 + og * 32 + c] = s;
    }
}

// ---------------------------------------------------------------------------
// fc (R12 frozen): (g_pp/1024) @ fc_w.T + fc_b, * mask -> g_h1
// ---------------------------------------------------------------------------
#define FC_SMEM_BYTES ((128 * 256 + 8 * 128) * 4)

__global__ void __launch_bounds__(256) fc_kernel(const float* __restrict__ fcw,
                                                 const float* __restrict__ fcb,
                                                 const float* __restrict__ mask) {
    extern __shared__ __align__(16) float smf[];
    float* ws = smf;
    float* ps = smf + 128 * 256;
    const int row0 = blockIdx.x * 8, tid = threadIdx.x;

    for (int i = tid; i < 128 * 256; i += 256) {
        int o = i >> 7, d = i & 127;
        ws[d * 256 + o] = fcw[i];
    }
    for (int i = tid; i < 8 * 128; i += 256)
        ps[i] = g_pp[row0 * 128 + i] * (1.f / 1024.f);
    __syncthreads();

    const int o = tid;
    float acc[8];
    float bb = fcb[o];
#pragma unroll
    for (int rr = 0; rr < 8; rr++) acc[rr] = bb;
    for (int d = 0; d < 128; d++) {
        float wv = ws[d * 256 + o];
#pragma unroll
        for (int rr = 0; rr < 8; rr++) acc[rr] = fmaf(ps[rr * 128 + d], wv, acc[rr]);
    }
#pragma unroll
    for (int rr = 0; rr < 8; rr++) {
        int row = row0 + rr;
        g_h1[row * 256 + o] = acc[rr] * mask[row];
    }
}

// ---------------------------------------------------------------------------
// SAGE, split-D: 512 thr; o = tid % OUTD, d-range split across 512/OUTD
// groups; partials (8 acc + v) combined once via smem.
// out = h @ W2^T + [cs @ lw^T / 31 + lb]
// dyn smem: HS 32*260 | CS 256 | PT 512*9   = 52736 B
// ---------------------------------------------------------------------------
#define SAGE_SMEM ((32 * 260 + 256 + 512 * 9) * 4)

template <int OUTD, bool RELU, bool FROM_H1>
__global__ void __launch_bounds__(512) sage_kernel(const float* __restrict__ lb,
                                                   float* __restrict__ out) {
    extern __shared__ __align__(16) float sg[];
    float* hs = sg;                 // [32][260]
    float* CS = sg + 32 * 260;      // [256]
    float* PT = CS + 256;           // [512][9]
    const int b = blockIdx.x, tid = threadIdx.x;
    const int n0 = blockIdx.y * 8;
    const float* hb = (FROM_H1 ? g_h1 : g_h2) + b * 8192;

    for (int i = tid; i < 8192; i += 512) {
        int nn = i >> 8, d = i & 255;
        hs[nn * 260 + d] = hb[i];
    }
    __syncthreads();
    if (tid < 256) {
        float s = 0.f;
#pragma unroll
        for (int nn = 0; nn < 32; nn++) s += hs[nn * 260 + tid];
        CS[tid] = s;
    }
    __syncthreads();

    constexpr int NS = 512 / OUTD;       // 2 (sage1) or 4 (sage2)
    constexpr int DL = 256 / NS;         // 128 or 64
    const int o = tid % OUTD;
    const int grp = tid / OUTD;
    const int d0 = grp * DL;

    const float* lt = (OUTD == 256) ? g_l1t : g_l2t;
    const float* wt = (OUTD == 256) ? g_w21t : g_w22t;

    float v = 0.f;
    for (int d = d0; d < d0 + DL; d += 4)
        v += CS[d] * lt[d * OUTD + o] + CS[d + 1] * lt[(d + 1) * OUTD + o] +
             CS[d + 2] * lt[(d + 2) * OUTD + o] +
             CS[d + 3] * lt[(d + 3) * OUTD + o];

    float acc[8];
#pragma unroll
    for (int nn = 0; nn < 8; nn++) acc[nn] = 0.f;
    for (int d = d0; d < d0 + DL; d++) {
        float w = wt[d * OUTD + o];
#pragma unroll
        for (int nn = 0; nn < 8; nn++)
            acc[nn] = fmaf(hs[(n0 + nn) * 260 + d], w, acc[nn]);
    }

    // publish partials (group 0 keeps its own in registers)
    if (grp > 0) {
        float* p = &PT[tid * 9];
#pragma unroll
        for (int nn = 0; nn < 8; nn++) p[nn] = acc[nn];
        p[8] = v;
    }
    __syncthreads();

    if (tid < OUTD) {
        float vt = v;
        float a[8];
#pragma unroll
        for (int nn = 0; nn < 8; nn++) a[nn] = acc[nn];
#pragma unroll
        for (int h = 1; h < NS; h++) {
            const float* p = &PT[(h * OUTD + o) * 9];
#pragma unroll
            for (int nn = 0; nn < 8; nn++) a[nn] += p[nn];
            vt += p[8];
        }
        float init = vt * (1.f / 31.f) + lb[o];
#pragma unroll
        for (int nn = 0; nn < 8; nn++) {
            float r = a[nn] + init;
            if (RELU) r = fmaxf(r, 0.f);
            if (OUTD == 256)
                g_h2[(b * 32 + n0 + nn) * 256 + o] = r;
            else
                out[(b * 32 + n0 + nn) * OUTD + o] = r;
        }
    }
}

// ---------------------------------------------------------------------------
extern "C" void kernel_launch(void* const* d_in, const int* in_sizes, int n_in,
                              void* d_out, int out_size) {
    const float* x    = (const float*)d_in[0];
    const float* mask = (const float*)d_in[1];
    const float* c1w  = (const float*)d_in[2];
    const float* c1b  = (const float*)d_in[3];
    const float* c2w  = (const float*)d_in[4];
    const float* c2b  = (const float*)d_in[5];
    const float* fcw  = (const float*)d_in[6];
    const float* fcb  = (const float*)d_in[7];
    const float* s1lw = (const float*)d_in[8];
    const float* s1lb = (const float*)d_in[9];
    const float* s1rw = (const float*)d_in[10];
    const float* s2lw = (const float*)d_in[11];
    const float* s2lb = (const float*)d_in[12];
    const float* s2rw = (const float*)d_in[13];
    float* out = (float*)d_out;

    cudaFuncSetAttribute(conv2_mma, cudaFuncAttributeMaxDynamicSharedMemorySize,
                         C2_SMEM);
    cudaFuncSetAttribute(fc_kernel, cudaFuncAttributeMaxDynamicSharedMemorySize,
                         FC_SMEM_BYTES);
    cudaFuncSetAttribute(sage_kernel<256, true, true>,
                         cudaFuncAttributeMaxDynamicSharedMemorySize, SAGE_SMEM);
    cudaFuncSetAttribute(sage_kernel<128, false, false>,
                         cudaFuncAttributeMaxDynamicSharedMemorySize, SAGE_SMEM);

    prep_all<<<672, 256>>>(c2w, s1lw, s1rw, s2lw, s2rw);
    conv1_kernel<<<1024, 256>>>(x, c1w, c1b);
    conv2_mma<<<1024, 512, C2_SMEM>>>(c2b);
    fc_kernel<<<128, 256, FC_SMEM_BYTES>>>(fcw, fcb, mask);
    sage_kernel<256, true, true><<<dim3(32, 4), 512, SAGE_SMEM>>>(s1lb, out);
    sage_kernel<128, false, false><<<dim3(32, 4), 512, SAGE_SMEM>>>(s2lb, out);
}